// round 8
// baseline (speedup 1.0000x reference)
#include <cuda_runtime.h>
#include <cuda_bf16.h>
#include <mma.h>

using namespace nvcuda;

#define NN   32768
#define DD   128
#define BB   64
#define NPGC 512
#define EE   524288
#define KCL  5
#define H2D  256
#define CBN  512

typedef __nv_bfloat16 bf16;

// ---------------- scratch (device globals; no runtime allocation) ----------------
__device__ float g_h[NN*DD];
__device__ float g_S[NN*KCL];
__device__ float g_res[BB*DD];
__device__ int   g_off[NN+1], g_srcl[EE];
__device__ bf16  g_w1hi[3*DD*H2D], g_w1lo[3*DD*H2D];
__device__ bf16  g_w2hi[3*H2D*DD], g_w2lo[3*H2D*DD];
__device__ bf16  g_pwhi[DD*128],   g_pwlo[DD*128];   // partitioner W1 padded 50->128
__device__ float g_pb1[128];

__device__ __forceinline__ void bsplit(float v, bf16& hi, bf16& lo) {
    hi = __float2bfloat16(v);
    lo = __float2bfloat16(v - __bfloat162float(hi));
}

__device__ __forceinline__ void cpa16(void* dst, const void* src) {
    unsigned sa = (unsigned)__cvta_generic_to_shared(dst);
    asm volatile("cp.async.cg.shared.global [%0], [%1], 16;\n" :: "r"(sa), "l"(src));
}
#define CPA_COMMIT() asm volatile("cp.async.commit_group;\n" ::: "memory")
#define CPA_WAIT0()  asm volatile("cp.async.wait_group 0;\n" ::: "memory")

// ---------------- per-graph CSR build (counting sort in smem) + zero g_res ----------------
__global__ void csr_kernel(const int* __restrict__ ei) {
    __shared__ int cnt[512];
    __shared__ int offs[512];
    int g = blockIdx.x, t = threadIdx.x;       // 64 blocks x 512 threads
    cnt[t] = 0;
    if (t < 128) g_res[g*128 + t] = 0.0f;
    __syncthreads();
    int ebase = g*8192;
    int nbase = g*512;
    #pragma unroll
    for (int i = 0; i < 16; i++) {
        int e = ebase + t + i*512;
        int d = ei[EE + e] - nbase;            // local dst (edges stay in-graph)
        atomicAdd(&cnt[d], 1);
    }
    __syncthreads();
    offs[t] = cnt[t];
    __syncthreads();
    for (int off = 1; off < 512; off <<= 1) {
        int v = (t >= off) ? offs[t-off] : 0;
        __syncthreads();
        offs[t] += v;
        __syncthreads();
    }
    int excl = offs[t] - cnt[t];
    g_off[nbase + t] = ebase + excl;
    if (g == BB-1 && t == 511) g_off[NN] = EE;
    cnt[t] = excl;                              // reuse as scatter cursor
    __syncthreads();
    #pragma unroll
    for (int i = 0; i < 16; i++) {
        int e = ebase + t + i*512;
        int d = ei[EE + e] - nbase;
        int p = atomicAdd(&cnt[d], 1);
        g_srcl[ebase + p] = ei[e];
    }
}

// ---------------- prep (weight splits) + embedding, grid-stride ----------------
__global__ void prep_embed(const int* __restrict__ x, const float* __restrict__ emb,
                           const float* __restrict__ gW1, const float* __restrict__ gW2,
                           const float* __restrict__ pW1, const float* __restrict__ pb1) {
    const int tot = NN*DD + 3*DD*H2D + 3*H2D*DD + DD*128 + 128;
    for (int i0 = blockIdx.x*256 + threadIdx.x; i0 < tot; i0 += gridDim.x*256) {
        int i = i0;
        if (i < NN*DD) { g_h[i] = emb[x[i >> 7]*DD + (i & 127)]; continue; }
        i -= NN*DD;
        if (i < 3*DD*H2D) { bsplit(gW1[i], g_w1hi[i], g_w1lo[i]); continue; }
        i -= 3*DD*H2D;
        if (i < 3*H2D*DD) { bsplit(gW2[i], g_w2hi[i], g_w2lo[i]); continue; }
        i -= 3*H2D*DD;
        if (i < DD*128) {
            int rw = i >> 7, cl = i & 127;
            float v = (cl < 50) ? pW1[rw*50 + cl] : 0.0f;
            bsplit(v, g_pwhi[i], g_pwlo[i]);
            continue;
        }
        i -= DD*128;
        if (i < 128) g_pb1[i] = (i < 50) ? pb1[i] : 0.0f;
    }
}

// ---------------- fused GIN layer, M=64 tile, occ-2, cp.async double-buffered weights ----------------
// 512 threads, 64 nodes/CTA, smem 102400 B -> 2 CTAs/SM.
//   [0,17408)        sZh 64x136 bf16
//   [17408,34816)    sZl
//   [34816,102400)   W1 ping-pong: 2 buffers x (hi 32x264 + lo 32x264) = 2 x 33792 B
//   hidden aliases [0,67584) at pitch 264
//   [67584,102400)   gemm2: W2 ping-pong 2 x (hi 32x136 + lo 32x136) = 2 x 17408 B; then scrF f32 64x132
//   partitioner: sPh [34816,52224), sPl [52224,69632); w2s [101376,102396)
#define ZLD  136
#define WLD  264
#define W2LD 136
#define GIN2_SMEM 102400

__global__ __launch_bounds__(512, 2)
void ginlayer(const bf16* __restrict__ W1h, const bf16* __restrict__ W1l,
              const bf16* __restrict__ W2h, const bf16* __restrict__ W2l,
              const float* __restrict__ b1, const float* __restrict__ b2,
              const float* __restrict__ gamma, const float* __restrict__ beta,
              const bf16* __restrict__ Ph, const bf16* __restrict__ Pl,
              const float* __restrict__ pbias, const float* __restrict__ pW2,
              const float* __restrict__ pb2, int last)
{
    extern __shared__ __align__(16) char smem[];
    bf16*  sZh   = (bf16*)smem;
    bf16*  sZl   = sZh + 64*ZLD;
    bf16*  wbase = sZl + 64*ZLD;                 // byte 34816; W1 ping-pong
    bf16*  sHh   = (bf16*)smem;
    bf16*  sHl   = sHh + 64*WLD;
    float* scrF  = (float*)(smem + 4*64*WLD);    // byte 67584
    bf16*  w2base= (bf16*)(smem + 4*64*WLD);     // W2 ping-pong
    bf16*  sPh   = (bf16*)(smem + 34816);
    bf16*  sPl   = sPh + 64*W2LD;
    float* w2s   = (float*)(smem + 101376);

    int t = threadIdx.x, w = t >> 5, lane = t & 31;
    int m0 = blockIdx.x*64;

    // ---- prefetch W1 chunk 0 (overlaps gather) ----
    {
        #pragma unroll
        for (int i = 0; i < 4; i++) {
            int idx = t + i*512;                 // 0..2047: hi then lo, 1024 uint4 each
            int m = idx >> 10, j = idx & 1023;
            int r = j >> 5, p = j & 31;
            const bf16* src = (m ? W1l : W1h) + (size_t)r*256 + p*8;
            bf16* dst = wbase + m*32*WLD + r*WLD + p*8;
            cpa16(dst, src);
        }
        CPA_COMMIT();
    }

    // ---- Phase A: gather z (4 nodes per warp) ----
    {
        const float4* __restrict__ h4 = (const float4*)g_h;
        #pragma unroll
        for (int i = 0; i < 4; i++) {
            int r = w*4 + i;
            int node = m0 + r;
            float4 a = h4[(size_t)node*32 + lane];
            int e0 = g_off[node], e1 = g_off[node+1];
            int j = e0;
            for (; j + 4 <= e1; j += 4) {
                int s0 = g_srcl[j+0], s1 = g_srcl[j+1], s2 = g_srcl[j+2], s3 = g_srcl[j+3];
                float4 v0 = h4[(size_t)s0*32 + lane];
                float4 v1 = h4[(size_t)s1*32 + lane];
                float4 v2 = h4[(size_t)s2*32 + lane];
                float4 v3 = h4[(size_t)s3*32 + lane];
                a.x += (v0.x + v1.x) + (v2.x + v3.x);
                a.y += (v0.y + v1.y) + (v2.y + v3.y);
                a.z += (v0.z + v1.z) + (v2.z + v3.z);
                a.w += (v0.w + v1.w) + (v2.w + v3.w);
            }
            for (; j < e1; j++) {
                int s = g_srcl[j];
                float4 v = h4[(size_t)s*32 + lane];
                a.x += v.x; a.y += v.y; a.z += v.z; a.w += v.w;
            }
            __nv_bfloat162* ph = (__nv_bfloat162*)(sZh + r*ZLD);
            __nv_bfloat162* pl = (__nv_bfloat162*)(sZl + r*ZLD);
            bf16 h0,l0,h1,l1;
            bsplit(a.x, h0, l0); bsplit(a.y, h1, l1);
            ph[lane*2]   = __halves2bfloat162(h0, h1);
            pl[lane*2]   = __halves2bfloat162(l0, l1);
            bsplit(a.z, h0, l0); bsplit(a.w, h1, l1);
            ph[lane*2+1] = __halves2bfloat162(h0, h1);
            pl[lane*2+1] = __halves2bfloat162(l0, l1);
        }
    }
    CPA_WAIT0();
    __syncthreads();

    // ---- Phase B: gemm1  hidden[64x256] = z[64x128] @ W1[128x256], 4 chunks, double-buffered ----
    int wm1 = w >> 3, wn1 = w & 7;               // 2 x 8 warps, warp tile 32x32
    {
        wmma::fragment<wmma::accumulator,16,16,16,float> acc1[2][2];
        #pragma unroll
        for (int i = 0; i < 2; i++)
            #pragma unroll
            for (int j = 0; j < 2; j++)
                wmma::fill_fragment(acc1[i][j], 0.0f);

        #pragma unroll
        for (int c = 0; c < 4; c++) {
            const bf16* curH = wbase + (c&1)*(2*32*WLD);
            const bf16* curL = curH + 32*WLD;
            if (c < 3) {
                bf16* nb = wbase + ((c+1)&1)*(2*32*WLD);
                #pragma unroll
                for (int i = 0; i < 4; i++) {
                    int idx = t + i*512;
                    int m = idx >> 10, j = idx & 1023;
                    int r = j >> 5, p = j & 31;
                    const bf16* src = (m ? W1l : W1h) + (size_t)((c+1)*32 + r)*256 + p*8;
                    bf16* dst = nb + m*32*WLD + r*WLD + p*8;
                    cpa16(dst, src);
                }
                CPA_COMMIT();
            }
            #pragma unroll
            for (int kb = 0; kb < 2; kb++) {
                int ko = c*32 + kb*16;
                wmma::fragment<wmma::matrix_a,16,16,16,bf16,wmma::row_major> ah[2], al[2];
                #pragma unroll
                for (int i = 0; i < 2; i++) {
                    wmma::load_matrix_sync(ah[i], sZh + (wm1*32 + i*16)*ZLD + ko, ZLD);
                    wmma::load_matrix_sync(al[i], sZl + (wm1*32 + i*16)*ZLD + ko, ZLD);
                }
                wmma::fragment<wmma::matrix_b,16,16,16,bf16,wmma::row_major> bh[2], bl[2];
                #pragma unroll
                for (int j = 0; j < 2; j++) {
                    wmma::load_matrix_sync(bh[j], curH + (kb*16)*WLD + wn1*32 + j*16, WLD);
                    wmma::load_matrix_sync(bl[j], curL + (kb*16)*WLD + wn1*32 + j*16, WLD);
                }
                #pragma unroll
                for (int i = 0; i < 2; i++)
                    #pragma unroll
                    for (int j = 0; j < 2; j++) {
                        wmma::mma_sync(acc1[i][j], ah[i], bh[j], acc1[i][j]);
                        wmma::mma_sync(acc1[i][j], ah[i], bl[j], acc1[i][j]);
                        wmma::mma_sync(acc1[i][j], al[i], bh[j], acc1[i][j]);
                    }
            }
            if (c < 3) CPA_WAIT0();
            __syncthreads();
        }

        // ---- Phase C: hidden epilogue (bias+relu+split), 2 N-halves via scrF ----
        #pragma unroll
        for (int r = 0; r < 2; r++) {
            if (r) __syncthreads();
            if ((wn1 >> 2) == r) {
                #pragma unroll
                for (int i = 0; i < 2; i++)
                    #pragma unroll
                    for (int j = 0; j < 2; j++)
                        wmma::store_matrix_sync(scrF + (wm1*32 + i*16)*132 + (wn1 & 3)*32 + j*16,
                                                acc1[i][j], 132, wmma::mem_row_major);
            }
            __syncthreads();
            #pragma unroll 4
            for (int it = 0; it < 16; it++) {
                int idx = t + it*512;
                int rr = idx >> 7, c = idx & 127;
                int C = r*128 + c;
                float v = fmaxf(scrF[rr*132 + c] + __ldg(b1 + C), 0.0f);
                bf16 hi, lo; bsplit(v, hi, lo);
                sHh[rr*WLD + C] = hi;
                sHl[rr*WLD + C] = lo;
            }
        }
    }
    __syncthreads();

    // ---- Phase D: gemm2  out[64x128] = hidden[64x256] @ W2[256x128], 8 chunks, double-buffered ----
    {
        int wm = w & 3, wn = w >> 2;             // 4 x 4 warps, warp tile 16x32
        wmma::fragment<wmma::accumulator,16,16,16,float> acc2[2];
        #pragma unroll
        for (int j = 0; j < 2; j++) wmma::fill_fragment(acc2[j], 0.0f);

        // stage chunk 0
        {
            #pragma unroll
            for (int i = 0; i < 2; i++) {
                int idx = t + i*512;             // 0..1023: hi then lo, 512 uint4 each
                int m = idx >> 9, j = idx & 511;
                int r = j >> 4, p = j & 15;
                const bf16* src = (m ? W2l : W2h) + (size_t)r*128 + p*8;
                bf16* dst = w2base + m*32*W2LD + r*W2LD + p*8;
                cpa16(dst, src);
            }
            CPA_COMMIT();
        }
        CPA_WAIT0();
        __syncthreads();

        #pragma unroll
        for (int c2 = 0; c2 < 8; c2++) {
            const bf16* cH = w2base + (c2&1)*(2*32*W2LD);
            const bf16* cL = cH + 32*W2LD;
            if (c2 < 7) {
                bf16* nb = w2base + ((c2+1)&1)*(2*32*W2LD);
                #pragma unroll
                for (int i = 0; i < 2; i++) {
                    int idx = t + i*512;
                    int m = idx >> 9, j = idx & 511;
                    int r = j >> 4, p = j & 15;
                    const bf16* src = (m ? W2l : W2h) + (size_t)((c2+1)*32 + r)*128 + p*8;
                    bf16* dst = nb + m*32*W2LD + r*W2LD + p*8;
                    cpa16(dst, src);
                }
                CPA_COMMIT();
            }
            #pragma unroll
            for (int kb = 0; kb < 2; kb++) {
                int ko = c2*32 + kb*16;
                wmma::fragment<wmma::matrix_a,16,16,16,bf16,wmma::row_major> ah, al;
                wmma::load_matrix_sync(ah, sHh + (wm*16)*WLD + ko, WLD);
                wmma::load_matrix_sync(al, sHl + (wm*16)*WLD + ko, WLD);
                wmma::fragment<wmma::matrix_b,16,16,16,bf16,wmma::row_major> bh0, bh1, bl0, bl1;
                int nb2 = wn*32;
                wmma::load_matrix_sync(bh0, cH + (kb*16)*W2LD + nb2,      W2LD);
                wmma::load_matrix_sync(bh1, cH + (kb*16)*W2LD + nb2 + 16, W2LD);
                wmma::load_matrix_sync(bl0, cL + (kb*16)*W2LD + nb2,      W2LD);
                wmma::load_matrix_sync(bl1, cL + (kb*16)*W2LD + nb2 + 16, W2LD);
                wmma::mma_sync(acc2[0], ah, bh0, acc2[0]);
                wmma::mma_sync(acc2[1], ah, bh1, acc2[1]);
                wmma::mma_sync(acc2[0], ah, bl0, acc2[0]);
                wmma::mma_sync(acc2[1], ah, bl1, acc2[1]);
                wmma::mma_sync(acc2[0], al, bh0, acc2[0]);
                wmma::mma_sync(acc2[1], al, bh1, acc2[1]);
            }
            if (c2 < 7) CPA_WAIT0();
            __syncthreads();
        }
        #pragma unroll
        for (int j = 0; j < 2; j++)
            wmma::store_matrix_sync(scrF + (wm*16)*132 + wn*32 + j*16, acc2[j],
                                    132, wmma::mem_row_major);
        __syncthreads();
    }

    // ---- Phase E: final epilogue (bias + BN [+relu]) -> g_h [+ act-split to smem, residue] ----
    const float BNS = 0.99999500003749971f;    // 1/sqrt(1+1e-5)
    {
        int ccol = t & 127;
        float rsum = 0.0f;
        #pragma unroll 4
        for (int it = 0; it < 16; it++) {
            int idx = t + it*512;
            int r = idx >> 7;                      // 0..63
            float v = scrF[r*132 + ccol] + __ldg(b2 + ccol);
            v = v*(BNS*__ldg(gamma + ccol)) + __ldg(beta + ccol);
            if (!last) v = fmaxf(v, 0.0f);
            size_t gi = (size_t)(m0 + r)*128 + ccol;
            g_h[gi] = v;
            if (last) {
                bf16 hi, lo; bsplit(v, hi, lo);
                sZh[r*ZLD + ccol] = hi;            // act split -> z region (hidden dead)
                sZl[r*ZLD + ccol] = lo;
                rsum += v;
            }
        }
        if (last)
            atomicAdd(&g_res[(m0 >> 9)*128 + ccol], rsum);
    }

    if (!last) return;

    // ---- Phase F: fused partitioner  cl[64x128] = act[64x128] @ pW1[128x128] ----
    {
        wmma::fragment<wmma::accumulator,16,16,16,float> acc3[2];
        #pragma unroll
        for (int i = 0; i < 2; i++) wmma::fill_fragment(acc3[i], 0.0f);

        #pragma unroll
        for (int c = 0; c < 2; c++) {
            __syncthreads();
            #pragma unroll
            for (int i = 0; i < 2; i++) {            // 1024 uint4 per matrix
                int idx = t + i*512;
                int r = idx >> 4, p = idx & 15;
                *(uint4*)(sPh + r*W2LD + p*8) = *(const uint4*)(Ph + (size_t)(c*64 + r)*128 + p*8);
                *(uint4*)(sPl + r*W2LD + p*8) = *(const uint4*)(Pl + (size_t)(c*64 + r)*128 + p*8);
            }
            __syncthreads();
            #pragma unroll
            for (int kb = 0; kb < 4; kb++) {
                wmma::fragment<wmma::matrix_a,16,16,16,bf16,wmma::row_major> ah[2], al[2];
                #pragma unroll
                for (int i = 0; i < 2; i++) {
                    wmma::load_matrix_sync(ah[i], sZh + (wm1*32 + i*16)*ZLD + c*64 + kb*16, ZLD);
                    wmma::load_matrix_sync(al[i], sZl + (wm1*32 + i*16)*ZLD + c*64 + kb*16, ZLD);
                }
                wmma::fragment<wmma::matrix_b,16,16,16,bf16,wmma::row_major> bh, bl;
                wmma::load_matrix_sync(bh, sPh + (kb*16)*W2LD + wn1*16, W2LD);
                wmma::load_matrix_sync(bl, sPl + (kb*16)*W2LD + wn1*16, W2LD);
                #pragma unroll
                for (int i = 0; i < 2; i++) {
                    wmma::mma_sync(acc3[i], ah[i], bh, acc3[i]);
                    wmma::mma_sync(acc3[i], ah[i], bl, acc3[i]);
                    wmma::mma_sync(acc3[i], al[i], bh, acc3[i]);
                }
            }
        }
        __syncthreads();
        #pragma unroll
        for (int i = 0; i < 2; i++)
            wmma::store_matrix_sync(scrF + (wm1*32 + i*16)*132 + wn1*16, acc3[i],
                                    132, wmma::mem_row_major);
        if (t < 255) w2s[t] = (t < 250) ? pW2[t] : pb2[t - 250];
        __syncthreads();

        if (t < 64) {
            float cr[50];
            #pragma unroll
            for (int j = 0; j < 50; j++)
                cr[j] = fmaxf(scrF[t*132 + j] + pbias[j], 0.0f);
            float l[5];
            #pragma unroll
            for (int k = 0; k < 5; k++) {
                float a = w2s[250 + k];
                #pragma unroll
                for (int j = 0; j < 50; j++) a += cr[j]*w2s[j*5 + k];
                l[k] = a;
            }
            float m = l[0];
            #pragma unroll
            for (int k = 1; k < 5; k++) m = fmaxf(m, l[k]);
            float e[5], s = 0.0f;
            #pragma unroll
            for (int k = 0; k < 5; k++) { e[k] = expf(l[k] - m); s += e[k]; }
            float inv = 1.0f/s;
            #pragma unroll
            for (int k = 0; k < 5; k++) g_S[(size_t)(m0 + t)*5 + k] = e[k]*inv;
        }
    }
}

// ---------------- finale: cf pooling + VQ + attention/gate/classifier, one block per graph ----------------
__global__ void finale_kernel(const float* __restrict__ codebook,
                              const float* __restrict__ Wq, const float* __restrict__ Wk,
                              const float* __restrict__ Wv, const float* __restrict__ Wo,
                              const float* __restrict__ gW1, const float* __restrict__ gb1,
                              const float* __restrict__ gW2, const float* __restrict__ gb2,
                              const float* __restrict__ cW1, const float* __restrict__ cb1,
                              const float* __restrict__ cW2, const float* __restrict__ cb2,
                              const float* __restrict__ cW3, const float* __restrict__ cb3,
                              float* __restrict__ out)
{
    __shared__ __align__(16) float sh[64*128];       // cf staging, later tail scratch
    __shared__ float sS[64*5];
    __shared__ __align__(16) float cfv[5*128];
    __shared__ float zq5[5*128];
    __shared__ float wbest[5][4];
    __shared__ int   widx[5][4];
    __shared__ int   bidx[5];

    int g = blockIdx.x, t = threadIdx.x;             // 640 threads
    int k = t >> 7, c = t & 127;

    // ---- cf: soft-cluster pooling ----
    {
        float acc = 0.0f, ss = 0.0f;
        for (int ch = 0; ch < 8; ch++) {
            int nb = ch*64;
            const float* hb = g_h + ((size_t)g*NPGC + nb)*DD;
            for (int i = t; i < 64*128; i += 640) sh[i] = hb[i];
            const float* sb = g_S + ((size_t)g*NPGC + nb)*5;
            for (int i = t; i < 320; i += 640) sS[i] = sb[i];
            __syncthreads();
            for (int n2 = 0; n2 < 64; n2++) {
                float s = sS[n2*5 + k];
                acc += s*sh[n2*128 + c];
                ss  += s;
            }
            __syncthreads();
        }
        cfv[k*128 + c] = acc/(ss + 1e-6f);
    }
    __syncthreads();

    // ---- VQ: nearest codebook row per cluster (5 rows x 4 warps each) ----
    {
        int w4 = c >> 5, lane = c & 31;
        float4 fv = ((const float4*)(cfv + k*128))[lane];
        float best = 3.4e38f;
        int bi = 0;
        for (int rr = w4; rr < CBN; rr += 4) {
            const float4* cb4 = (const float4*)(codebook + (size_t)rr*128);
            float4 cv = cb4[lane];
            float dx = cv.x - fv.x, dy = cv.y - fv.y, dz = cv.z - fv.z, dw = cv.w - fv.w;
            float d = dx*dx + dy*dy + dz*dz + dw*dw;
            #pragma unroll
            for (int o = 16; o; o >>= 1) d += __shfl_xor_sync(0xffffffff, d, o);
            if (d < best) { best = d; bi = rr; }
        }
        if (lane == 0) { wbest[k][w4] = best; widx[k][w4] = bi; }
        __syncthreads();
        if (t < 5) {
            float bb = wbest[t][0]; int ii = widx[t][0];
            for (int j = 1; j < 4; j++)
                if (wbest[t][j] < bb || (wbest[t][j] == bb && widx[t][j] < ii)) { bb = wbest[t][j]; ii = widx[t][j]; }
            bidx[t] = ii;
        }
        __syncthreads();
        zq5[k*128 + c] = codebook[(size_t)bidx[k]*128 + c];
    }
    __syncthreads();

    // ---- tail: attention + gate + classifier (sh region reused as scratch) ----
    float* r    = sh;            // 128
    float* qv   = sh + 128;      // 128
    float* kk   = sh + 256;      // 640
    float* vv   = sh + 896;      // 640
    float* sc   = sh + 1536;     // 20
    float* aw   = sh + 1568;     // 20
    float* attv = sh + 1600;     // 128
    float* attn = sh + 1728;     // 128
    float* g1   = sh + 1856;     // 64
    float* fus  = sh + 1920;     // 128
    float* z1   = sh + 2048;     // 512
    float* z2   = sh + 2560;     // 256

    if (t < 128) r[t] = g_res[g*128 + t]*(1.0f/NPGC);
    __syncthreads();

    if (t < 128) {
        float a = 0.0f;
        for (int k2 = 0; k2 < 128; k2++) a += r[k2]*Wq[k2*128 + t];
        qv[t] = a;
        float a5[5] = {0,0,0,0,0};
        for (int k2 = 0; k2 < 128; k2++) {
            float wv2 = Wk[k2*128 + t];
            #pragma unroll
            for (int j = 0; j < 5; j++) a5[j] += zq5[j*128 + k2]*wv2;
        }
        #pragma unroll
        for (int j = 0; j < 5; j++) kk[j*128 + t] = a5[j];
        float b5[5] = {0,0,0,0,0};
        for (int k2 = 0; k2 < 128; k2++) {
            float wv2 = Wv[k2*128 + t];
            #pragma unroll
            for (int j = 0; j < 5; j++) b5[j] += zq5[j*128 + k2]*wv2;
        }
        #pragma unroll
        for (int j = 0; j < 5; j++) vv[j*128 + t] = b5[j];
    }
    __syncthreads();

    if (t < 20) {
        int hh = t/5, j = t%5;
        float s = 0.0f;
        for (int d2 = 0; d2 < 32; d2++) s += qv[hh*32 + d2]*kk[j*128 + hh*32 + d2];
        sc[t] = s*0.17677669529663687f;              // 1/sqrt(32)
    }
    __syncthreads();
    if (t < 4) {
        float m = -1e30f;
        #pragma unroll
        for (int j = 0; j < 5; j++) m = fmaxf(m, sc[t*5 + j]);
        float e[5], s = 0.0f;
        #pragma unroll
        for (int j = 0; j < 5; j++) { e[j] = expf(sc[t*5 + j] - m); s += e[j]; }
        float inv = 1.0f/s;
        #pragma unroll
        for (int j = 0; j < 5; j++) aw[t*5 + j] = e[j]*inv;
    }
    __syncthreads();
    if (t < 128) {
        int hh = t >> 5;
        float a = 0.0f;
        #pragma unroll
        for (int j = 0; j < 5; j++) a += aw[hh*5 + j]*vv[j*128 + t];
        attv[t] = a;
    }
    __syncthreads();
    if (t < 128) {
        float a = 0.0f;
        for (int k2 = 0; k2 < 128; k2++) a += attv[k2]*Wo[k2*128 + t];
        attn[t] = a;
    }
    __syncthreads();
    if (t < 64) {
        float a = gb1[t];
        for (int k2 = 0; k2 < 128; k2++) a += r[k2]*gW1[k2*64 + t];
        for (int k2 = 0; k2 < 128; k2++) a += attn[k2]*gW1[(128 + k2)*64 + t];
        g1[t] = fmaxf(a, 0.0f);
    }
    __syncthreads();
    if (t < 128) {
        float a = gb2[t];
        for (int k2 = 0; k2 < 64; k2++) a += g1[k2]*gW2[k2*128 + t];
        float gg = 1.0f/(1.0f + expf(-a));
        fus[t] = gg*r[t] + (1.0f - gg)*attn[t];
    }
    __syncthreads();
    if (t < 512) {
        float a = cb1[t];
        for (int k2 = 0; k2 < 128; k2++) a += fus[k2]*cW1[k2*512 + t];
        z1[t] = fmaxf(a, 0.0f);
    }
    __syncthreads();
    if (t < 256) {
        float a = cb2[t];
        for (int k2 = 0; k2 < 512; k2++) a += z1[k2]*cW2[k2*256 + t];
        z2[t] = fmaxf(a, 0.0f);
    }
    __syncthreads();
    if (t < 2) {
        float a = cb3[t];
        for (int k2 = 0; k2 < 256; k2++) a += z2[k2]*cW3[k2*2 + t];
        out[g*2 + t] = a;
    }
}

// ---------------- host launch ----------------
extern "C" void kernel_launch(void* const* d_in, const int* in_sizes, int n_in,
                              void* d_out, int out_size) {
    (void)in_sizes; (void)n_in; (void)out_size;
    const int*   x     = (const int*)d_in[0];
    const int*   ei    = (const int*)d_in[1];
    const float* emb   = (const float*)d_in[3];
    const float* gW1   = (const float*)d_in[4];
    const float* gb1v  = (const float*)d_in[5];
    const float* gW2   = (const float*)d_in[6];
    const float* gb2v  = (const float*)d_in[7];
    const float* bng   = (const float*)d_in[8];
    const float* bnb   = (const float*)d_in[9];
    const float* pW1   = (const float*)d_in[10];
    const float* pb1   = (const float*)d_in[11];
    const float* pW2   = (const float*)d_in[12];
    const float* pb2   = (const float*)d_in[13];
    const float* Wq    = (const float*)d_in[14];
    const float* Wk    = (const float*)d_in[15];
    const float* Wv    = (const float*)d_in[16];
    const float* Wo    = (const float*)d_in[17];
    const float* gateW1= (const float*)d_in[18];
    const float* gateb1= (const float*)d_in[19];
    const float* gateW2= (const float*)d_in[20];
    const float* gateb2= (const float*)d_in[21];
    const float* cbk   = (const float*)d_in[22];
    const float* cW1   = (const float*)d_in[23];
    const float* cb1   = (const float*)d_in[24];
    const float* cW2   = (const float*)d_in[25];
    const float* cb2   = (const float*)d_in[26];
    const float* cW3   = (const float*)d_in[27];
    const float* cb3   = (const float*)d_in[28];
    float* out = (float*)d_out;

    bf16 *w1hi, *w1lo, *w2hi, *w2lo, *pwhi, *pwlo;
    float *ppb1;
    cudaGetSymbolAddress((void**)&w1hi, g_w1hi);
    cudaGetSymbolAddress((void**)&w1lo, g_w1lo);
    cudaGetSymbolAddress((void**)&w2hi, g_w2hi);
    cudaGetSymbolAddress((void**)&w2lo, g_w2lo);
    cudaGetSymbolAddress((void**)&pwhi, g_pwhi);
    cudaGetSymbolAddress((void**)&pwlo, g_pwlo);
    cudaGetSymbolAddress((void**)&ppb1, g_pb1);

    cudaFuncSetAttribute(ginlayer, cudaFuncAttributeMaxDynamicSharedMemorySize, GIN2_SMEM);

    csr_kernel<<<BB, 512>>>(ei);
    prep_embed<<<2048, 256>>>(x, emb, gW1, gW2, pW1, pb1);

    for (int l = 0; l < 3; l++) {
        ginlayer<<<NN/64, 512, GIN2_SMEM>>>(
            w1hi + (size_t)l*DD*H2D, w1lo + (size_t)l*DD*H2D,
            w2hi + (size_t)l*H2D*DD, w2lo + (size_t)l*H2D*DD,
            gb1v + l*H2D, gb2v + l*DD, bng + l*DD, bnb + l*DD,
            pwhi, pwlo, ppb1, pW2, pb2,
            (l == 2) ? 1 : 0);
    }

    finale_kernel<<<BB, 640>>>(cbk, Wq, Wk, Wv, Wo, gateW1, gateb1, gateW2, gateb2,
                               cW1, cb1, cW2, cb2, cW3, cb3, out);
}

// round 9
// speedup vs baseline: 1.0994x; 1.0994x over previous
#include <cuda_runtime.h>
#include <cuda_bf16.h>
#include <mma.h>

using namespace nvcuda;

#define NN   32768
#define DD   128
#define BB   64
#define NPGC 512
#define EE   524288
#define KCL  5
#define H2D  256
#define CBN  512

typedef __nv_bfloat16 bf16;

// ---------------- scratch (device globals; no runtime allocation) ----------------
__device__ float g_h[NN*DD];
__device__ float g_S[NN*KCL];
__device__ float g_res[BB*DD];
__device__ int   g_off[NN+1], g_srcl[EE];
__device__ bf16  g_w1hi[3*DD*H2D], g_w1lo[3*DD*H2D];
__device__ bf16  g_w2hi[3*H2D*DD], g_w2lo[3*H2D*DD];
__device__ bf16  g_pwhi[DD*128],   g_pwlo[DD*128];   // partitioner W1 padded 50->128
__device__ float g_pb1[128];

__device__ __forceinline__ void bsplit(float v, bf16& hi, bf16& lo) {
    hi = __float2bfloat16(v);
    lo = __float2bfloat16(v - __bfloat162float(hi));
}

__device__ __forceinline__ void cpa16(void* dst, const void* src) {
    unsigned sa = (unsigned)__cvta_generic_to_shared(dst);
    asm volatile("cp.async.cg.shared.global [%0], [%1], 16;\n" :: "r"(sa), "l"(src));
}
#define CPA_COMMIT() asm volatile("cp.async.commit_group;\n" ::: "memory")
#define CPA_WAIT0()  asm volatile("cp.async.wait_group 0;\n" ::: "memory")

// ---------------- per-graph CSR build (counting sort in smem) + zero g_res ----------------
__global__ void csr_kernel(const int* __restrict__ ei) {
    __shared__ int cnt[512];
    __shared__ int offs[512];
    int g = blockIdx.x, t = threadIdx.x;       // 64 blocks x 512 threads
    cnt[t] = 0;
    if (t < 128) g_res[g*128 + t] = 0.0f;
    __syncthreads();
    int ebase = g*8192;
    int nbase = g*512;
    #pragma unroll
    for (int i = 0; i < 16; i++) {
        int e = ebase + t + i*512;
        int d = ei[EE + e] - nbase;            // local dst (edges stay in-graph)
        atomicAdd(&cnt[d], 1);
    }
    __syncthreads();
    offs[t] = cnt[t];
    __syncthreads();
    for (int off = 1; off < 512; off <<= 1) {
        int v = (t >= off) ? offs[t-off] : 0;
        __syncthreads();
        offs[t] += v;
        __syncthreads();
    }
    int excl = offs[t] - cnt[t];
    g_off[nbase + t] = ebase + excl;
    if (g == BB-1 && t == 511) g_off[NN] = EE;
    cnt[t] = excl;                              // reuse as scatter cursor
    __syncthreads();
    #pragma unroll
    for (int i = 0; i < 16; i++) {
        int e = ebase + t + i*512;
        int d = ei[EE + e] - nbase;
        int p = atomicAdd(&cnt[d], 1);
        g_srcl[ebase + p] = ei[e];
    }
}

// ---------------- prep (weight splits) + embedding, grid-stride ----------------
__global__ void prep_embed(const int* __restrict__ x, const float* __restrict__ emb,
                           const float* __restrict__ gW1, const float* __restrict__ gW2,
                           const float* __restrict__ pW1, const float* __restrict__ pb1) {
    const int tot = NN*DD + 3*DD*H2D + 3*H2D*DD + DD*128 + 128;
    for (int i0 = blockIdx.x*256 + threadIdx.x; i0 < tot; i0 += gridDim.x*256) {
        int i = i0;
        if (i < NN*DD) { g_h[i] = emb[x[i >> 7]*DD + (i & 127)]; continue; }
        i -= NN*DD;
        if (i < 3*DD*H2D) { bsplit(gW1[i], g_w1hi[i], g_w1lo[i]); continue; }
        i -= 3*DD*H2D;
        if (i < 3*H2D*DD) { bsplit(gW2[i], g_w2hi[i], g_w2lo[i]); continue; }
        i -= 3*H2D*DD;
        if (i < DD*128) {
            int rw = i >> 7, cl = i & 127;
            float v = (cl < 50) ? pW1[rw*50 + cl] : 0.0f;
            bsplit(v, g_pwhi[i], g_pwlo[i]);
            continue;
        }
        i -= DD*128;
        if (i < 128) g_pb1[i] = (i < 50) ? pb1[i] : 0.0f;
    }
}

// ---------------- fused GIN layer, M=32 tile, 256 threads, occ-4 ----------------
// smem 52736 B -> 4 CTAs/SM, 8 warps/CTA (4 independent barrier domains per SM).
//   [0,8704)       sZh 32x136 bf16    [8704,17408) sZl
//   [17408,51200)  W1 ping-pong: 2 x (hi 16x264 + lo 16x264) = 2 x 16896 B
//   hidden aliases: sHh [0,16896) 32x264, sHl [16896,33792)
//   [33792,50688)  scrF 32x132 f32  /  W2 ping-pong 2 x (hi 16x136 + lo 16x136) = 2 x 8704 B
//   partitioner: sPh/sPl [17408,34816); scrFp [34816,51712); w2s [51712,52732)
#define ZLD  136
#define WLD  264
#define W2LD 136
#define GIN_SMEM 52736

__global__ __launch_bounds__(256, 4)
void ginlayer(const bf16* __restrict__ W1h, const bf16* __restrict__ W1l,
              const bf16* __restrict__ W2h, const bf16* __restrict__ W2l,
              const float* __restrict__ b1, const float* __restrict__ b2,
              const float* __restrict__ gamma, const float* __restrict__ beta,
              const bf16* __restrict__ Ph, const bf16* __restrict__ Pl,
              const float* __restrict__ pbias, const float* __restrict__ pW2,
              const float* __restrict__ pb2, int last)
{
    extern __shared__ __align__(16) char smem[];
    bf16*  sZh   = (bf16*)smem;
    bf16*  sZl   = sZh + 32*ZLD;                 // 4352 elems
    bf16*  wbase = (bf16*)(smem + 17408);        // W1 ping-pong, buf = 8448 elems
    bf16*  sHh   = (bf16*)smem;                  // 32x264
    bf16*  sHl   = sHh + 32*WLD;                 // 8448 elems
    float* scrF  = (float*)(smem + 33792);
    bf16*  w2base= (bf16*)(smem + 33792);        // W2 ping-pong, buf = 4352 elems
    bf16*  sPh   = (bf16*)(smem + 17408);
    bf16*  sPl   = sPh + 32*W2LD;                // 4352 elems
    float* scrFp = (float*)(smem + 34816);
    float* w2s   = (float*)(smem + 51712);

    int t = threadIdx.x, w = t >> 5, lane = t & 31;
    int m0 = blockIdx.x*32;

    // ---- prefetch W1 chunk 0 (16 K-rows, overlaps gather) ----
    {
        #pragma unroll
        for (int i = 0; i < 4; i++) {
            int idx = t + i*256;                 // 0..1023: hi 512 uint4, lo 512
            int m = idx >> 9, j = idx & 511;
            int r = j >> 5, p = j & 31;
            const bf16* src = (m ? W1l : W1h) + (size_t)r*256 + p*8;
            bf16* dst = wbase + m*(16*WLD) + r*WLD + p*8;
            cpa16(dst, src);
        }
        CPA_COMMIT();
    }

    // ---- Phase A: gather z (4 nodes per warp) ----
    {
        const float4* __restrict__ h4 = (const float4*)g_h;
        #pragma unroll
        for (int i = 0; i < 4; i++) {
            int r = w*4 + i;
            int node = m0 + r;
            float4 a = h4[(size_t)node*32 + lane];
            int e0 = g_off[node], e1 = g_off[node+1];
            int j = e0;
            for (; j + 4 <= e1; j += 4) {
                int s0 = g_srcl[j+0], s1 = g_srcl[j+1], s2 = g_srcl[j+2], s3 = g_srcl[j+3];
                float4 v0 = h4[(size_t)s0*32 + lane];
                float4 v1 = h4[(size_t)s1*32 + lane];
                float4 v2 = h4[(size_t)s2*32 + lane];
                float4 v3 = h4[(size_t)s3*32 + lane];
                a.x += (v0.x + v1.x) + (v2.x + v3.x);
                a.y += (v0.y + v1.y) + (v2.y + v3.y);
                a.z += (v0.z + v1.z) + (v2.z + v3.z);
                a.w += (v0.w + v1.w) + (v2.w + v3.w);
            }
            for (; j < e1; j++) {
                int s = g_srcl[j];
                float4 v = h4[(size_t)s*32 + lane];
                a.x += v.x; a.y += v.y; a.z += v.z; a.w += v.w;
            }
            __nv_bfloat162* ph = (__nv_bfloat162*)(sZh + r*ZLD);
            __nv_bfloat162* pl = (__nv_bfloat162*)(sZl + r*ZLD);
            bf16 h0,l0,h1,l1;
            bsplit(a.x, h0, l0); bsplit(a.y, h1, l1);
            ph[lane*2]   = __halves2bfloat162(h0, h1);
            pl[lane*2]   = __halves2bfloat162(l0, l1);
            bsplit(a.z, h0, l0); bsplit(a.w, h1, l1);
            ph[lane*2+1] = __halves2bfloat162(h0, h1);
            pl[lane*2+1] = __halves2bfloat162(l0, l1);
        }
    }
    CPA_WAIT0();
    __syncthreads();

    // ---- Phase B: gemm1  hidden[32x256] = z[32x128] @ W1[128x256], 8 chunks of 16 ----
    {
        // warp w covers rows 0..31, cols w*32
        wmma::fragment<wmma::accumulator,16,16,16,float> acc1[2][2];
        #pragma unroll
        for (int i = 0; i < 2; i++)
            #pragma unroll
            for (int j = 0; j < 2; j++)
                wmma::fill_fragment(acc1[i][j], 0.0f);

        #pragma unroll
        for (int c = 0; c < 8; c++) {
            const bf16* curH = wbase + (c&1)*8448;
            const bf16* curL = curH + 16*WLD;
            if (c < 7) {
                bf16* nb = wbase + ((c+1)&1)*8448;
                #pragma unroll
                for (int i = 0; i < 4; i++) {
                    int idx = t + i*256;
                    int m = idx >> 9, j = idx & 511;
                    int r = j >> 5, p = j & 31;
                    const bf16* src = (m ? W1l : W1h) + (size_t)((c+1)*16 + r)*256 + p*8;
                    bf16* dst = nb + m*(16*WLD) + r*WLD + p*8;
                    cpa16(dst, src);
                }
                CPA_COMMIT();
            }
            {
                int ko = c*16;
                wmma::fragment<wmma::matrix_a,16,16,16,bf16,wmma::row_major> ah[2], al[2];
                #pragma unroll
                for (int i = 0; i < 2; i++) {
                    wmma::load_matrix_sync(ah[i], sZh + (i*16)*ZLD + ko, ZLD);
                    wmma::load_matrix_sync(al[i], sZl + (i*16)*ZLD + ko, ZLD);
                }
                wmma::fragment<wmma::matrix_b,16,16,16,bf16,wmma::row_major> bh[2], bl[2];
                #pragma unroll
                for (int j = 0; j < 2; j++) {
                    wmma::load_matrix_sync(bh[j], curH + w*32 + j*16, WLD);
                    wmma::load_matrix_sync(bl[j], curL + w*32 + j*16, WLD);
                }
                #pragma unroll
                for (int i = 0; i < 2; i++)
                    #pragma unroll
                    for (int j = 0; j < 2; j++) {
                        wmma::mma_sync(acc1[i][j], ah[i], bh[j], acc1[i][j]);
                        wmma::mma_sync(acc1[i][j], ah[i], bl[j], acc1[i][j]);
                        wmma::mma_sync(acc1[i][j], al[i], bh[j], acc1[i][j]);
                    }
            }
            if (c < 7) CPA_WAIT0();
            __syncthreads();
        }

        // ---- Phase C: hidden epilogue (bias+relu+split), 2 N-halves via scrF ----
        #pragma unroll
        for (int r = 0; r < 2; r++) {
            if (r) __syncthreads();
            if ((w >> 2) == r) {
                #pragma unroll
                for (int i = 0; i < 2; i++)
                    #pragma unroll
                    for (int j = 0; j < 2; j++)
                        wmma::store_matrix_sync(scrF + (i*16)*132 + (w & 3)*32 + j*16,
                                                acc1[i][j], 132, wmma::mem_row_major);
            }
            __syncthreads();
            #pragma unroll 4
            for (int it = 0; it < 16; it++) {
                int idx = t + it*256;
                int rr = idx >> 7, c = idx & 127;
                int C = r*128 + c;
                float v = fmaxf(scrF[rr*132 + c] + __ldg(b1 + C), 0.0f);
                bf16 hi, lo; bsplit(v, hi, lo);
                sHh[rr*WLD + C] = hi;
                sHl[rr*WLD + C] = lo;
            }
        }
    }
    __syncthreads();

    // ---- Phase D: gemm2  out[32x128] = hidden[32x256] @ W2[256x128], 16 chunks of 16 ----
    {
        int wm = w & 1, wn = w >> 1;             // 2 x 4 warps, warp tile 16x32
        wmma::fragment<wmma::accumulator,16,16,16,float> acc2[2];
        #pragma unroll
        for (int j = 0; j < 2; j++) wmma::fill_fragment(acc2[j], 0.0f);

        // stage chunk 0
        {
            #pragma unroll
            for (int i = 0; i < 2; i++) {
                int idx = t + i*256;             // 0..511: hi 256 uint4, lo 256
                int m = idx >> 8, j = idx & 255;
                int r = j >> 4, p = j & 15;
                const bf16* src = (m ? W2l : W2h) + (size_t)r*128 + p*8;
                bf16* dst = w2base + m*(16*W2LD) + r*W2LD + p*8;
                cpa16(dst, src);
            }
            CPA_COMMIT();
        }
        CPA_WAIT0();
        __syncthreads();

        #pragma unroll
        for (int c2 = 0; c2 < 16; c2++) {
            const bf16* cH = w2base + (c2&1)*4352;
            const bf16* cL = cH + 16*W2LD;
            if (c2 < 15) {
                bf16* nb = w2base + ((c2+1)&1)*4352;
                #pragma unroll
                for (int i = 0; i < 2; i++) {
                    int idx = t + i*256;
                    int m = idx >> 8, j = idx & 255;
                    int r = j >> 4, p = j & 15;
                    const bf16* src = (m ? W2l : W2h) + (size_t)((c2+1)*16 + r)*128 + p*8;
                    bf16* dst = nb + m*(16*W2LD) + r*W2LD + p*8;
                    cpa16(dst, src);
                }
                CPA_COMMIT();
            }
            {
                int ko = c2*16;
                wmma::fragment<wmma::matrix_a,16,16,16,bf16,wmma::row_major> ah, al;
                wmma::load_matrix_sync(ah, sHh + (wm*16)*WLD + ko, WLD);
                wmma::load_matrix_sync(al, sHl + (wm*16)*WLD + ko, WLD);
                wmma::fragment<wmma::matrix_b,16,16,16,bf16,wmma::row_major> bh0, bh1, bl0, bl1;
                int nb2 = wn*32;
                wmma::load_matrix_sync(bh0, cH + nb2,      W2LD);
                wmma::load_matrix_sync(bh1, cH + nb2 + 16, W2LD);
                wmma::load_matrix_sync(bl0, cL + nb2,      W2LD);
                wmma::load_matrix_sync(bl1, cL + nb2 + 16, W2LD);
                wmma::mma_sync(acc2[0], ah, bh0, acc2[0]);
                wmma::mma_sync(acc2[1], ah, bh1, acc2[1]);
                wmma::mma_sync(acc2[0], ah, bl0, acc2[0]);
                wmma::mma_sync(acc2[1], ah, bl1, acc2[1]);
                wmma::mma_sync(acc2[0], al, bh0, acc2[0]);
                wmma::mma_sync(acc2[1], al, bh1, acc2[1]);
            }
            if (c2 < 15) CPA_WAIT0();
            __syncthreads();
        }
        #pragma unroll
        for (int j = 0; j < 2; j++)
            wmma::store_matrix_sync(scrF + (wm*16)*132 + wn*32 + j*16, acc2[j],
                                    132, wmma::mem_row_major);
        __syncthreads();
    }

    // ---- Phase E: final epilogue (bias + BN [+relu]) -> g_h [+ act-split to smem, residue] ----
    const float BNS = 0.99999500003749971f;    // 1/sqrt(1+1e-5)
    {
        int ccol = t & 127;
        float rsum = 0.0f;
        #pragma unroll 4
        for (int it = 0; it < 16; it++) {
            int idx = t + it*256;
            int r = idx >> 7;                      // 0..31
            float v = scrF[r*132 + ccol] + __ldg(b2 + ccol);
            v = v*(BNS*__ldg(gamma + ccol)) + __ldg(beta + ccol);
            if (!last) v = fmaxf(v, 0.0f);
            size_t gi = (size_t)(m0 + r)*128 + ccol;
            g_h[gi] = v;
            if (last) {
                bf16 hi, lo; bsplit(v, hi, lo);
                sZh[r*ZLD + ccol] = hi;            // act split -> z region (hidden dead)
                sZl[r*ZLD + ccol] = lo;
                rsum += v;
            }
        }
        if (last)
            atomicAdd(&g_res[(m0 >> 9)*128 + ccol], rsum);
    }

    if (!last) return;

    // ---- Phase F: fused partitioner  cl[32x128] = act[32x128] @ pW1[128x128], 4 chunks of 32 ----
    {
        int wm = w & 1, wn = w >> 1;             // 2 x 4 warps, warp tile 16x32
        wmma::fragment<wmma::accumulator,16,16,16,float> acc3[2];
        #pragma unroll
        for (int i = 0; i < 2; i++) wmma::fill_fragment(acc3[i], 0.0f);

        #pragma unroll
        for (int c = 0; c < 4; c++) {
            __syncthreads();
            #pragma unroll
            for (int i = 0; i < 4; i++) {        // 1024 uint4: hi 512, lo 512
                int idx = t + i*256;
                int m = idx >> 9, j = idx & 511;
                int r = j >> 4, p = j & 15;
                const bf16* src = (m ? Pl : Ph) + (size_t)(c*32 + r)*128 + p*8;
                bf16* dst = (m ? sPl : sPh) + r*W2LD + p*8;
                *(uint4*)dst = *(const uint4*)src;
            }
            __syncthreads();
            #pragma unroll
            for (int kb = 0; kb < 2; kb++) {
                wmma::fragment<wmma::matrix_a,16,16,16,bf16,wmma::row_major> ah, al;
                wmma::load_matrix_sync(ah, sZh + (wm*16)*ZLD + c*32 + kb*16, ZLD);
                wmma::load_matrix_sync(al, sZl + (wm*16)*ZLD + c*32 + kb*16, ZLD);
                wmma::fragment<wmma::matrix_b,16,16,16,bf16,wmma::row_major> bh0, bh1, bl0, bl1;
                int nb2 = wn*32;
                wmma::load_matrix_sync(bh0, sPh + (kb*16)*W2LD + nb2,      W2LD);
                wmma::load_matrix_sync(bh1, sPh + (kb*16)*W2LD + nb2 + 16, W2LD);
                wmma::load_matrix_sync(bl0, sPl + (kb*16)*W2LD + nb2,      W2LD);
                wmma::load_matrix_sync(bl1, sPl + (kb*16)*W2LD + nb2 + 16, W2LD);
                wmma::mma_sync(acc3[0], ah, bh0, acc3[0]);
                wmma::mma_sync(acc3[1], ah, bh1, acc3[1]);
                wmma::mma_sync(acc3[0], ah, bl0, acc3[0]);
                wmma::mma_sync(acc3[1], ah, bl1, acc3[1]);
                wmma::mma_sync(acc3[0], al, bh0, acc3[0]);
                wmma::mma_sync(acc3[1], al, bh1, acc3[1]);
            }
        }
        __syncthreads();
        #pragma unroll
        for (int j = 0; j < 2; j++)
            wmma::store_matrix_sync(scrFp + (wm*16)*132 + wn*32 + j*16, acc3[j],
                                    132, wmma::mem_row_major);
        if (t < 255) w2s[t] = (t < 250) ? pW2[t] : pb2[t - 250];
        __syncthreads();

        if (t < 32) {
            float cr[50];
            #pragma unroll
            for (int j = 0; j < 50; j++)
                cr[j] = fmaxf(scrFp[t*132 + j] + pbias[j], 0.0f);
            float l[5];
            #pragma unroll
            for (int k = 0; k < 5; k++) {
                float a = w2s[250 + k];
                #pragma unroll
                for (int j = 0; j < 50; j++) a += cr[j]*w2s[j*5 + k];
                l[k] = a;
            }
            float m = l[0];
            #pragma unroll
            for (int k = 1; k < 5; k++) m = fmaxf(m, l[k]);
            float e[5], s = 0.0f;
            #pragma unroll
            for (int k = 0; k < 5; k++) { e[k] = expf(l[k] - m); s += e[k]; }
            float inv = 1.0f/s;
            #pragma unroll
            for (int k = 0; k < 5; k++) g_S[(size_t)(m0 + t)*5 + k] = e[k]*inv;
        }
    }
}

// ---------------- finale: cf pooling + VQ + attention/gate/classifier, one block per graph ----------------
__global__ void finale_kernel(const float* __restrict__ codebook,
                              const float* __restrict__ Wq, const float* __restrict__ Wk,
                              const float* __restrict__ Wv, const float* __restrict__ Wo,
                              const float* __restrict__ gW1, const float* __restrict__ gb1,
                              const float* __restrict__ gW2, const float* __restrict__ gb2,
                              const float* __restrict__ cW1, const float* __restrict__ cb1,
                              const float* __restrict__ cW2, const float* __restrict__ cb2,
                              const float* __restrict__ cW3, const float* __restrict__ cb3,
                              float* __restrict__ out)
{
    __shared__ __align__(16) float sh[64*128];       // cf staging, later tail scratch
    __shared__ float sS[64*5];
    __shared__ __align__(16) float cfv[5*128];
    __shared__ float zq5[5*128];
    __shared__ float wbest[5][4];
    __shared__ int   widx[5][4];
    __shared__ int   bidx[5];

    int g = blockIdx.x, t = threadIdx.x;             // 640 threads
    int k = t >> 7, c = t & 127;

    // ---- cf: soft-cluster pooling ----
    {
        float acc = 0.0f, ss = 0.0f;
        for (int ch = 0; ch < 8; ch++) {
            int nb = ch*64;
            const float* hb = g_h + ((size_t)g*NPGC + nb)*DD;
            for (int i = t; i < 64*128; i += 640) sh[i] = hb[i];
            const float* sb = g_S + ((size_t)g*NPGC + nb)*5;
            for (int i = t; i < 320; i += 640) sS[i] = sb[i];
            __syncthreads();
            for (int n2 = 0; n2 < 64; n2++) {
                float s = sS[n2*5 + k];
                acc += s*sh[n2*128 + c];
                ss  += s;
            }
            __syncthreads();
        }
        cfv[k*128 + c] = acc/(ss + 1e-6f);
    }
    __syncthreads();

    // ---- VQ: nearest codebook row per cluster (5 rows x 4 warps each) ----
    {
        int w4 = c >> 5, lane = c & 31;
        float4 fv = ((const float4*)(cfv + k*128))[lane];
        float best = 3.4e38f;
        int bi = 0;
        for (int rr = w4; rr < CBN; rr += 4) {
            const float4* cb4 = (const float4*)(codebook + (size_t)rr*128);
            float4 cv = cb4[lane];
            float dx = cv.x - fv.x, dy = cv.y - fv.y, dz = cv.z - fv.z, dw = cv.w - fv.w;
            float d = dx*dx + dy*dy + dz*dz + dw*dw;
            #pragma unroll
            for (int o = 16; o; o >>= 1) d += __shfl_xor_sync(0xffffffff, d, o);
            if (d < best) { best = d; bi = rr; }
        }
        if (lane == 0) { wbest[k][w4] = best; widx[k][w4] = bi; }
        __syncthreads();
        if (t < 5) {
            float bb = wbest[t][0]; int ii = widx[t][0];
            for (int j = 1; j < 4; j++)
                if (wbest[t][j] < bb || (wbest[t][j] == bb && widx[t][j] < ii)) { bb = wbest[t][j]; ii = widx[t][j]; }
            bidx[t] = ii;
        }
        __syncthreads();
        zq5[k*128 + c] = codebook[(size_t)bidx[k]*128 + c];
    }
    __syncthreads();

    // ---- tail: attention + gate + classifier (sh region reused as scratch) ----
    float* r    = sh;            // 128
    float* qv   = sh + 128;      // 128
    float* kk   = sh + 256;      // 640
    float* vv   = sh + 896;      // 640
    float* sc   = sh + 1536;     // 20
    float* aw   = sh + 1568;     // 20
    float* attv = sh + 1600;     // 128
    float* attn = sh + 1728;     // 128
    float* g1   = sh + 1856;     // 64
    float* fus  = sh + 1920;     // 128
    float* z1   = sh + 2048;     // 512
    float* z2   = sh + 2560;     // 256

    if (t < 128) r[t] = g_res[g*128 + t]*(1.0f/NPGC);
    __syncthreads();

    if (t < 128) {
        float a = 0.0f;
        for (int k2 = 0; k2 < 128; k2++) a += r[k2]*Wq[k2*128 + t];
        qv[t] = a;
        float a5[5] = {0,0,0,0,0};
        for (int k2 = 0; k2 < 128; k2++) {
            float wv2 = Wk[k2*128 + t];
            #pragma unroll
            for (int j = 0; j < 5; j++) a5[j] += zq5[j*128 + k2]*wv2;
        }
        #pragma unroll
        for (int j = 0; j < 5; j++) kk[j*128 + t] = a5[j];
        float b5[5] = {0,0,0,0,0};
        for (int k2 = 0; k2 < 128; k2++) {
            float wv2 = Wv[k2*128 + t];
            #pragma unroll
            for (int j = 0; j < 5; j++) b5[j] += zq5[j*128 + k2]*wv2;
        }
        #pragma unroll
        for (int j = 0; j < 5; j++) vv[j*128 + t] = b5[j];
    }
    __syncthreads();

    if (t < 20) {
        int hh = t/5, j = t%5;
        float s = 0.0f;
        for (int d2 = 0; d2 < 32; d2++) s += qv[hh*32 + d2]*kk[j*128 + hh*32 + d2];
        sc[t] = s*0.17677669529663687f;              // 1/sqrt(32)
    }
    __syncthreads();
    if (t < 4) {
        float m = -1e30f;
        #pragma unroll
        for (int j = 0; j < 5; j++) m = fmaxf(m, sc[t*5 + j]);
        float e[5], s = 0.0f;
        #pragma unroll
        for (int j = 0; j < 5; j++) { e[j] = expf(sc[t*5 + j] - m); s += e[j]; }
        float inv = 1.0f/s;
        #pragma unroll
        for (int j = 0; j < 5; j++) aw[t*5 + j] = e[j]*inv;
    }
    __syncthreads();
    if (t < 128) {
        int hh = t >> 5;
        float a = 0.0f;
        #pragma unroll
        for (int j = 0; j < 5; j++) a += aw[hh*5 + j]*vv[j*128 + t];
        attv[t] = a;
    }
    __syncthreads();
    if (t < 128) {
        float a = 0.0f;
        for (int k2 = 0; k2 < 128; k2++) a += attv[k2]*Wo[k2*128 + t];
        attn[t] = a;
    }
    __syncthreads();
    if (t < 64) {
        float a = gb1[t];
        for (int k2 = 0; k2 < 128; k2++) a += r[k2]*gW1[k2*64 + t];
        for (int k2 = 0; k2 < 128; k2++) a += attn[k2]*gW1[(128 + k2)*64 + t];
        g1[t] = fmaxf(a, 0.0f);
    }
    __syncthreads();
    if (t < 128) {
        float a = gb2[t];
        for (int k2 = 0; k2 < 64; k2++) a += g1[k2]*gW2[k2*128 + t];
        float gg = 1.0f/(1.0f + expf(-a));
        fus[t] = gg*r[t] + (1.0f - gg)*attn[t];
    }
    __syncthreads();
    if (t < 512) {
        float a = cb1[t];
        for (int k2 = 0; k2 < 128; k2++) a += fus[k2]*cW1[k2*512 + t];
        z1[t] = fmaxf(a, 0.0f);
    }
    __syncthreads();
    if (t < 256) {
        float a = cb2[t];
        for (int k2 = 0; k2 < 512; k2++) a += z1[k2]*cW2[k2*256 + t];
        z2[t] = fmaxf(a, 0.0f);
    }
    __syncthreads();
    if (t < 2) {
        float a = cb3[t];
        for (int k2 = 0; k2 < 256; k2++) a += z2[k2]*cW3[k2*2 + t];
        out[g*2 + t] = a;
    }
}

// ---------------- host launch ----------------
extern "C" void kernel_launch(void* const* d_in, const int* in_sizes, int n_in,
                              void* d_out, int out_size) {
    (void)in_sizes; (void)n_in; (void)out_size;
    const int*   x     = (const int*)d_in[0];
    const int*   ei    = (const int*)d_in[1];
    const float* emb   = (const float*)d_in[3];
    const float* gW1   = (const float*)d_in[4];
    const float* gb1v  = (const float*)d_in[5];
    const float* gW2   = (const float*)d_in[6];
    const float* gb2v  = (const float*)d_in[7];
    const float* bng   = (const float*)d_in[8];
    const float* bnb   = (const float*)d_in[9];
    const float* pW1   = (const float*)d_in[10];
    const float* pb1   = (const float*)d_in[11];
    const float* pW2   = (const float*)d_in[12];
    const float* pb2   = (const float*)d_in[13];
    const float* Wq    = (const float*)d_in[14];
    const float* Wk    = (const float*)d_in[15];
    const float* Wv    = (const float*)d_in[16];
    const float* Wo    = (const float*)d_in[17];
    const float* gateW1= (const float*)d_in[18];
    const float* gateb1= (const float*)d_in[19];
    const float* gateW2= (const float*)d_in[20];
    const float* gateb2= (const float*)d_in[21];
    const float* cbk   = (const float*)d_in[22];
    const float* cW1   = (const float*)d_in[23];
    const float* cb1   = (const float*)d_in[24];
    const float* cW2   = (const float*)d_in[25];
    const float* cb2   = (const float*)d_in[26];
    const float* cW3   = (const float*)d_in[27];
    const float* cb3   = (const float*)d_in[28];
    float* out = (float*)d_out;

    bf16 *w1hi, *w1lo, *w2hi, *w2lo, *pwhi, *pwlo;
    float *ppb1;
    cudaGetSymbolAddress((void**)&w1hi, g_w1hi);
    cudaGetSymbolAddress((void**)&w1lo, g_w1lo);
    cudaGetSymbolAddress((void**)&w2hi, g_w2hi);
    cudaGetSymbolAddress((void**)&w2lo, g_w2lo);
    cudaGetSymbolAddress((void**)&pwhi, g_pwhi);
    cudaGetSymbolAddress((void**)&pwlo, g_pwlo);
    cudaGetSymbolAddress((void**)&ppb1, g_pb1);

    cudaFuncSetAttribute(ginlayer, cudaFuncAttributeMaxDynamicSharedMemorySize, GIN_SMEM);

    csr_kernel<<<BB, 512>>>(ei);
    prep_embed<<<2048, 256>>>(x, emb, gW1, gW2, pW1, pb1);

    for (int l = 0; l < 3; l++) {
        ginlayer<<<NN/32, 256, GIN_SMEM>>>(
            w1hi + (size_t)l*DD*H2D, w1lo + (size_t)l*DD*H2D,
            w2hi + (size_t)l*H2D*DD, w2lo + (size_t)l*H2D*DD,
            gb1v + l*H2D, gb2v + l*DD, bng + l*DD, bnb + l*DD,
            pwhi, pwlo, ppb1, pW2, pb2,
            (l == 2) ? 1 : 0);
    }

    finale_kernel<<<BB, 640>>>(cbk, Wq, Wk, Wv, Wo, gateW1, gateb1, gateW2, gateb2,
                               cW1, cb1, cW2, cb2, cW3, cb3, out);
}

// round 10
// speedup vs baseline: 1.1360x; 1.0333x over previous
#include <cuda_runtime.h>
#include <cuda_bf16.h>
#include <mma.h>

using namespace nvcuda;

#define NN   32768
#define DD   128
#define BB   64
#define NPGC 512
#define EE   524288
#define KCL  5
#define H2D  256
#define CBN  512

typedef __nv_bfloat16 bf16;

// ---------------- scratch (device globals; no runtime allocation) ----------------
__device__ float g_h[NN*DD];
__device__ float g_S[NN*KCL];
__device__ float g_res[BB*DD];
__device__ float g_cfnum[BB*KCL*DD];
__device__ float g_ssum[BB*KCL];
__device__ int   g_off[NN+1], g_srcl[EE];
__device__ bf16  g_w1hi[3*DD*H2D], g_w1lo[3*DD*H2D];
__device__ bf16  g_w2hi[3*H2D*DD], g_w2lo[3*H2D*DD];
__device__ bf16  g_pwhi[DD*128],   g_pwlo[DD*128];   // partitioner W1 padded 50->128
__device__ float g_pb1[128];

__device__ __forceinline__ void bsplit(float v, bf16& hi, bf16& lo) {
    hi = __float2bfloat16(v);
    lo = __float2bfloat16(v - __bfloat162float(hi));
}

__device__ __forceinline__ void cpa16(void* dst, const void* src) {
    unsigned sa = (unsigned)__cvta_generic_to_shared(dst);
    asm volatile("cp.async.cg.shared.global [%0], [%1], 16;\n" :: "r"(sa), "l"(src));
}
#define CPA_COMMIT() asm volatile("cp.async.commit_group;\n" ::: "memory")
#define CPA_WAIT0()  asm volatile("cp.async.wait_group 0;\n" ::: "memory")

// ---------------- setup: per-graph CSR (blocks 0..63) + prep/embed/zero (blocks 64+) ----------------
__global__ void setup_kernel(const int* __restrict__ ei,
                             const int* __restrict__ x, const float* __restrict__ emb,
                             const float* __restrict__ gW1, const float* __restrict__ gW2,
                             const float* __restrict__ pW1, const float* __restrict__ pb1) {
    int t = threadIdx.x;
    if (blockIdx.x < 64) {
        // ---- CSR build (counting sort in smem) + zero g_res ----
        __shared__ int cnt[512];
        __shared__ int offs[512];
        int g = blockIdx.x;
        cnt[t] = 0;
        if (t < 128) g_res[g*128 + t] = 0.0f;
        __syncthreads();
        int ebase = g*8192;
        int nbase = g*512;
        #pragma unroll
        for (int i = 0; i < 16; i++) {
            int e = ebase + t + i*512;
            int d = ei[EE + e] - nbase;            // local dst (edges stay in-graph)
            atomicAdd(&cnt[d], 1);
        }
        __syncthreads();
        offs[t] = cnt[t];
        __syncthreads();
        for (int off = 1; off < 512; off <<= 1) {
            int v = (t >= off) ? offs[t-off] : 0;
            __syncthreads();
            offs[t] += v;
            __syncthreads();
        }
        int excl = offs[t] - cnt[t];
        g_off[nbase + t] = ebase + excl;
        if (g == BB-1 && t == 511) g_off[NN] = EE;
        cnt[t] = excl;                              // reuse as scatter cursor
        __syncthreads();
        #pragma unroll
        for (int i = 0; i < 16; i++) {
            int e = ebase + t + i*512;
            int d = ei[EE + e] - nbase;
            int p = atomicAdd(&cnt[d], 1);
            g_srcl[ebase + p] = ei[e];
        }
        return;
    }
    // ---- prep: embedding + weight splits + zero cf accumulators, grid-stride ----
    const int tot = NN*DD + 3*DD*H2D + 3*H2D*DD + DD*128 + 128 + BB*KCL*DD + BB*KCL;
    int nb = gridDim.x - 64;
    for (int i0 = (blockIdx.x - 64)*512 + t; i0 < tot; i0 += nb*512) {
        int i = i0;
        if (i < NN*DD) { g_h[i] = emb[x[i >> 7]*DD + (i & 127)]; continue; }
        i -= NN*DD;
        if (i < 3*DD*H2D) { bsplit(gW1[i], g_w1hi[i], g_w1lo[i]); continue; }
        i -= 3*DD*H2D;
        if (i < 3*H2D*DD) { bsplit(gW2[i], g_w2hi[i], g_w2lo[i]); continue; }
        i -= 3*H2D*DD;
        if (i < DD*128) {
            int rw = i >> 7, cl = i & 127;
            float v = (cl < 50) ? pW1[rw*50 + cl] : 0.0f;
            bsplit(v, g_pwhi[i], g_pwlo[i]);
            continue;
        }
        i -= DD*128;
        if (i < 128) { g_pb1[i] = (i < 50) ? pb1[i] : 0.0f; continue; }
        i -= 128;
        if (i < BB*KCL*DD) { g_cfnum[i] = 0.0f; continue; }
        i -= BB*KCL*DD;
        g_ssum[i] = 0.0f;
    }
}

// ---------------- fused GIN layer, M=32 tile, 256 threads, occ-4 ----------------
#define ZLD  136
#define WLD  264
#define W2LD 136
#define GIN_SMEM 52736

__global__ __launch_bounds__(256, 4)
void ginlayer(const bf16* __restrict__ W1h, const bf16* __restrict__ W1l,
              const bf16* __restrict__ W2h, const bf16* __restrict__ W2l,
              const float* __restrict__ b1, const float* __restrict__ b2,
              const float* __restrict__ gamma, const float* __restrict__ beta,
              const bf16* __restrict__ Ph, const bf16* __restrict__ Pl,
              const float* __restrict__ pbias, const float* __restrict__ pW2,
              const float* __restrict__ pb2, int last)
{
    extern __shared__ __align__(16) char smem[];
    bf16*  sZh   = (bf16*)smem;
    bf16*  sZl   = sZh + 32*ZLD;                 // 4352 elems
    bf16*  wbase = (bf16*)(smem + 17408);        // W1 ping-pong, buf = 8448 elems
    bf16*  sHh   = (bf16*)smem;                  // 32x264
    bf16*  sHl   = sHh + 32*WLD;                 // 8448 elems
    float* scrF  = (float*)(smem + 33792);
    bf16*  w2base= (bf16*)(smem + 33792);        // W2 ping-pong, buf = 4352 elems
    bf16*  sPh   = (bf16*)(smem + 17408);
    bf16*  sPl   = sPh + 32*W2LD;                // 4352 elems
    float* scrFp = (float*)(smem + 34816);
    float* w2s   = (float*)(smem + 51712);

    int t = threadIdx.x, w = t >> 5, lane = t & 31;
    int m0 = blockIdx.x*32;

    // ---- prefetch W1 chunk 0 (16 K-rows, overlaps gather) ----
    {
        #pragma unroll
        for (int i = 0; i < 4; i++) {
            int idx = t + i*256;                 // 0..1023: hi 512 uint4, lo 512
            int m = idx >> 9, j = idx & 511;
            int r = j >> 5, p = j & 31;
            const bf16* src = (m ? W1l : W1h) + (size_t)r*256 + p*8;
            bf16* dst = wbase + m*(16*WLD) + r*WLD + p*8;
            cpa16(dst, src);
        }
        CPA_COMMIT();
    }

    // ---- Phase A: gather z (4 nodes per warp) ----
    {
        const float4* __restrict__ h4 = (const float4*)g_h;
        #pragma unroll
        for (int i = 0; i < 4; i++) {
            int r = w*4 + i;
            int node = m0 + r;
            float4 a = h4[(size_t)node*32 + lane];
            int e0 = g_off[node], e1 = g_off[node+1];
            int j = e0;
            for (; j + 4 <= e1; j += 4) {
                int s0 = g_srcl[j+0], s1 = g_srcl[j+1], s2 = g_srcl[j+2], s3 = g_srcl[j+3];
                float4 v0 = h4[(size_t)s0*32 + lane];
                float4 v1 = h4[(size_t)s1*32 + lane];
                float4 v2 = h4[(size_t)s2*32 + lane];
                float4 v3 = h4[(size_t)s3*32 + lane];
                a.x += (v0.x + v1.x) + (v2.x + v3.x);
                a.y += (v0.y + v1.y) + (v2.y + v3.y);
                a.z += (v0.z + v1.z) + (v2.z + v3.z);
                a.w += (v0.w + v1.w) + (v2.w + v3.w);
            }
            for (; j < e1; j++) {
                int s = g_srcl[j];
                float4 v = h4[(size_t)s*32 + lane];
                a.x += v.x; a.y += v.y; a.z += v.z; a.w += v.w;
            }
            __nv_bfloat162* ph = (__nv_bfloat162*)(sZh + r*ZLD);
            __nv_bfloat162* pl = (__nv_bfloat162*)(sZl + r*ZLD);
            bf16 h0,l0,h1,l1;
            bsplit(a.x, h0, l0); bsplit(a.y, h1, l1);
            ph[lane*2]   = __halves2bfloat162(h0, h1);
            pl[lane*2]   = __halves2bfloat162(l0, l1);
            bsplit(a.z, h0, l0); bsplit(a.w, h1, l1);
            ph[lane*2+1] = __halves2bfloat162(h0, h1);
            pl[lane*2+1] = __halves2bfloat162(l0, l1);
        }
    }
    CPA_WAIT0();
    __syncthreads();

    // ---- Phase B: gemm1  hidden[32x256] = z[32x128] @ W1[128x256], 8 chunks of 16 ----
    {
        wmma::fragment<wmma::accumulator,16,16,16,float> acc1[2][2];
        #pragma unroll
        for (int i = 0; i < 2; i++)
            #pragma unroll
            for (int j = 0; j < 2; j++)
                wmma::fill_fragment(acc1[i][j], 0.0f);

        #pragma unroll
        for (int c = 0; c < 8; c++) {
            const bf16* curH = wbase + (c&1)*8448;
            const bf16* curL = curH + 16*WLD;
            if (c < 7) {
                bf16* nb = wbase + ((c+1)&1)*8448;
                #pragma unroll
                for (int i = 0; i < 4; i++) {
                    int idx = t + i*256;
                    int m = idx >> 9, j = idx & 511;
                    int r = j >> 5, p = j & 31;
                    const bf16* src = (m ? W1l : W1h) + (size_t)((c+1)*16 + r)*256 + p*8;
                    bf16* dst = nb + m*(16*WLD) + r*WLD + p*8;
                    cpa16(dst, src);
                }
                CPA_COMMIT();
            }
            {
                int ko = c*16;
                wmma::fragment<wmma::matrix_a,16,16,16,bf16,wmma::row_major> ah[2], al[2];
                #pragma unroll
                for (int i = 0; i < 2; i++) {
                    wmma::load_matrix_sync(ah[i], sZh + (i*16)*ZLD + ko, ZLD);
                    wmma::load_matrix_sync(al[i], sZl + (i*16)*ZLD + ko, ZLD);
                }
                wmma::fragment<wmma::matrix_b,16,16,16,bf16,wmma::row_major> bh[2], bl[2];
                #pragma unroll
                for (int j = 0; j < 2; j++) {
                    wmma::load_matrix_sync(bh[j], curH + w*32 + j*16, WLD);
                    wmma::load_matrix_sync(bl[j], curL + w*32 + j*16, WLD);
                }
                #pragma unroll
                for (int i = 0; i < 2; i++)
                    #pragma unroll
                    for (int j = 0; j < 2; j++) {
                        wmma::mma_sync(acc1[i][j], ah[i], bh[j], acc1[i][j]);
                        wmma::mma_sync(acc1[i][j], ah[i], bl[j], acc1[i][j]);
                        wmma::mma_sync(acc1[i][j], al[i], bh[j], acc1[i][j]);
                    }
            }
            if (c < 7) CPA_WAIT0();
            __syncthreads();
        }

        // ---- Phase C: hidden epilogue (bias+relu+split), 2 N-halves via scrF ----
        #pragma unroll
        for (int r = 0; r < 2; r++) {
            if (r) __syncthreads();
            if ((w >> 2) == r) {
                #pragma unroll
                for (int i = 0; i < 2; i++)
                    #pragma unroll
                    for (int j = 0; j < 2; j++)
                        wmma::store_matrix_sync(scrF + (i*16)*132 + (w & 3)*32 + j*16,
                                                acc1[i][j], 132, wmma::mem_row_major);
            }
            __syncthreads();
            #pragma unroll 4
            for (int it = 0; it < 16; it++) {
                int idx = t + it*256;
                int rr = idx >> 7, c = idx & 127;
                int C = r*128 + c;
                float v = fmaxf(scrF[rr*132 + c] + __ldg(b1 + C), 0.0f);
                bf16 hi, lo; bsplit(v, hi, lo);
                sHh[rr*WLD + C] = hi;
                sHl[rr*WLD + C] = lo;
            }
        }
    }
    __syncthreads();

    // ---- Phase D: gemm2  out[32x128] = hidden[32x256] @ W2[256x128], 16 chunks of 16 ----
    {
        int wm = w & 1, wn = w >> 1;             // 2 x 4 warps, warp tile 16x32
        wmma::fragment<wmma::accumulator,16,16,16,float> acc2[2];
        #pragma unroll
        for (int j = 0; j < 2; j++) wmma::fill_fragment(acc2[j], 0.0f);

        // stage chunk 0
        {
            #pragma unroll
            for (int i = 0; i < 2; i++) {
                int idx = t + i*256;             // 0..511: hi 256 uint4, lo 256
                int m = idx >> 8, j = idx & 255;
                int r = j >> 4, p = j & 15;
                const bf16* src = (m ? W2l : W2h) + (size_t)r*128 + p*8;
                bf16* dst = w2base + m*(16*W2LD) + r*W2LD + p*8;
                cpa16(dst, src);
            }
            CPA_COMMIT();
        }
        CPA_WAIT0();
        __syncthreads();

        #pragma unroll
        for (int c2 = 0; c2 < 16; c2++) {
            const bf16* cH = w2base + (c2&1)*4352;
            const bf16* cL = cH + 16*W2LD;
            if (c2 < 15) {
                bf16* nb = w2base + ((c2+1)&1)*4352;
                #pragma unroll
                for (int i = 0; i < 2; i++) {
                    int idx = t + i*256;
                    int m = idx >> 8, j = idx & 255;
                    int r = j >> 4, p = j & 15;
                    const bf16* src = (m ? W2l : W2h) + (size_t)((c2+1)*16 + r)*128 + p*8;
                    bf16* dst = nb + m*(16*W2LD) + r*W2LD + p*8;
                    cpa16(dst, src);
                }
                CPA_COMMIT();
            }
            {
                int ko = c2*16;
                wmma::fragment<wmma::matrix_a,16,16,16,bf16,wmma::row_major> ah, al;
                wmma::load_matrix_sync(ah, sHh + (wm*16)*WLD + ko, WLD);
                wmma::load_matrix_sync(al, sHl + (wm*16)*WLD + ko, WLD);
                wmma::fragment<wmma::matrix_b,16,16,16,bf16,wmma::row_major> bh0, bh1, bl0, bl1;
                int nb2 = wn*32;
                wmma::load_matrix_sync(bh0, cH + nb2,      W2LD);
                wmma::load_matrix_sync(bh1, cH + nb2 + 16, W2LD);
                wmma::load_matrix_sync(bl0, cL + nb2,      W2LD);
                wmma::load_matrix_sync(bl1, cL + nb2 + 16, W2LD);
                wmma::mma_sync(acc2[0], ah, bh0, acc2[0]);
                wmma::mma_sync(acc2[1], ah, bh1, acc2[1]);
                wmma::mma_sync(acc2[0], ah, bl0, acc2[0]);
                wmma::mma_sync(acc2[1], ah, bl1, acc2[1]);
                wmma::mma_sync(acc2[0], al, bh0, acc2[0]);
                wmma::mma_sync(acc2[1], al, bh1, acc2[1]);
            }
            if (c2 < 15) CPA_WAIT0();
            __syncthreads();
        }
        #pragma unroll
        for (int j = 0; j < 2; j++)
            wmma::store_matrix_sync(scrF + (wm*16)*132 + wn*32 + j*16, acc2[j],
                                    132, wmma::mem_row_major);
        __syncthreads();
    }

    // ---- Phase E: final epilogue (bias + BN [+relu]) -> g_h [+ act-split to smem, residue] ----
    const float BNS = 0.99999500003749971f;    // 1/sqrt(1+1e-5)
    {
        int ccol = t & 127;
        float rsum = 0.0f;
        #pragma unroll 4
        for (int it = 0; it < 16; it++) {
            int idx = t + it*256;
            int r = idx >> 7;                      // 0..31
            float v = scrF[r*132 + ccol] + __ldg(b2 + ccol);
            v = v*(BNS*__ldg(gamma + ccol)) + __ldg(beta + ccol);
            if (!last) v = fmaxf(v, 0.0f);
            size_t gi = (size_t)(m0 + r)*128 + ccol;
            g_h[gi] = v;
            if (last) {
                bf16 hi, lo; bsplit(v, hi, lo);
                sZh[r*ZLD + ccol] = hi;            // act split -> z region (hidden dead)
                sZl[r*ZLD + ccol] = lo;
                rsum += v;
            }
        }
        if (last)
            atomicAdd(&g_res[(m0 >> 9)*128 + ccol], rsum);
    }

    if (!last) return;

    // ---- Phase F: fused partitioner  cl[32x128] = act[32x128] @ pW1[128x128], 4 chunks of 32 ----
    {
        int wm = w & 1, wn = w >> 1;             // 2 x 4 warps, warp tile 16x32
        wmma::fragment<wmma::accumulator,16,16,16,float> acc3[2];
        #pragma unroll
        for (int i = 0; i < 2; i++) wmma::fill_fragment(acc3[i], 0.0f);

        #pragma unroll
        for (int c = 0; c < 4; c++) {
            __syncthreads();
            #pragma unroll
            for (int i = 0; i < 4; i++) {        // 1024 uint4: hi 512, lo 512
                int idx = t + i*256;
                int m = idx >> 9, j = idx & 511;
                int r = j >> 4, p = j & 15;
                const bf16* src = (m ? Pl : Ph) + (size_t)(c*32 + r)*128 + p*8;
                bf16* dst = (m ? sPl : sPh) + r*W2LD + p*8;
                *(uint4*)dst = *(const uint4*)src;
            }
            __syncthreads();
            #pragma unroll
            for (int kb = 0; kb < 2; kb++) {
                wmma::fragment<wmma::matrix_a,16,16,16,bf16,wmma::row_major> ah, al;
                wmma::load_matrix_sync(ah, sZh + (wm*16)*ZLD + c*32 + kb*16, ZLD);
                wmma::load_matrix_sync(al, sZl + (wm*16)*ZLD + c*32 + kb*16, ZLD);
                wmma::fragment<wmma::matrix_b,16,16,16,bf16,wmma::row_major> bh0, bh1, bl0, bl1;
                int nb2 = wn*32;
                wmma::load_matrix_sync(bh0, sPh + (kb*16)*W2LD + nb2,      W2LD);
                wmma::load_matrix_sync(bh1, sPh + (kb*16)*W2LD + nb2 + 16, W2LD);
                wmma::load_matrix_sync(bl0, sPl + (kb*16)*W2LD + nb2,      W2LD);
                wmma::load_matrix_sync(bl1, sPl + (kb*16)*W2LD + nb2 + 16, W2LD);
                wmma::mma_sync(acc3[0], ah, bh0, acc3[0]);
                wmma::mma_sync(acc3[1], ah, bh1, acc3[1]);
                wmma::mma_sync(acc3[0], ah, bl0, acc3[0]);
                wmma::mma_sync(acc3[1], ah, bl1, acc3[1]);
                wmma::mma_sync(acc3[0], al, bh0, acc3[0]);
                wmma::mma_sync(acc3[1], al, bh1, acc3[1]);
            }
        }
        __syncthreads();
        #pragma unroll
        for (int j = 0; j < 2; j++)
            wmma::store_matrix_sync(scrFp + (wm*16)*132 + wn*32 + j*16, acc3[j],
                                    132, wmma::mem_row_major);
        if (t < 255) w2s[t] = (t < 250) ? pW2[t] : pb2[t - 250];
        __syncthreads();

        if (t < 32) {
            float cr[50];
            #pragma unroll
            for (int j = 0; j < 50; j++)
                cr[j] = fmaxf(scrFp[t*132 + j] + pbias[j], 0.0f);
            float l[5];
            #pragma unroll
            for (int k = 0; k < 5; k++) {
                float a = w2s[250 + k];
                #pragma unroll
                for (int j = 0; j < 50; j++) a += cr[j]*w2s[j*5 + k];
                l[k] = a;
            }
            float m = l[0];
            #pragma unroll
            for (int k = 1; k < 5; k++) m = fmaxf(m, l[k]);
            float e[5], s = 0.0f;
            #pragma unroll
            for (int k = 0; k < 5; k++) { e[k] = expf(l[k] - m); s += e[k]; }
            float inv = 1.0f/s;
            #pragma unroll
            for (int k = 0; k < 5; k++) g_S[(size_t)(m0 + t)*5 + k] = e[k]*inv;
        }
    }
}

// ---------------- cf partial: 8 blocks per graph accumulate S^T h and sum(S) ----------------
__global__ void cfpartial_kernel() {
    __shared__ __align__(16) float sh[64*128];
    __shared__ float sS[64*5];
    int g = blockIdx.x >> 3;
    int nb = (blockIdx.x & 7)*64;
    int t = threadIdx.x;                             // 640 threads
    int k = t >> 7, c = t & 127;

    const float* hb = g_h + ((size_t)g*NPGC + nb)*DD;
    for (int i = t; i < 64*128; i += 640) sh[i] = hb[i];
    const float* sb = g_S + ((size_t)g*NPGC + nb)*5;
    for (int i = t; i < 320; i += 640) sS[i] = sb[i];
    __syncthreads();

    float acc = 0.0f, ss = 0.0f;
    for (int n2 = 0; n2 < 64; n2++) {
        float s = sS[n2*5 + k];
        acc += s*sh[n2*128 + c];
        ss  += s;
    }
    atomicAdd(&g_cfnum[((size_t)g*5 + k)*128 + c], acc);
    if (c == 0) atomicAdd(&g_ssum[g*5 + k], ss);
}

// ---------------- finale: cf divide + VQ + attention/gate/classifier, one block per graph ----------------
__global__ void finale_kernel(const float* __restrict__ codebook,
                              const float* __restrict__ Wq, const float* __restrict__ Wk,
                              const float* __restrict__ Wv, const float* __restrict__ Wo,
                              const float* __restrict__ gW1, const float* __restrict__ gb1,
                              const float* __restrict__ gW2, const float* __restrict__ gb2,
                              const float* __restrict__ cW1, const float* __restrict__ cb1,
                              const float* __restrict__ cW2, const float* __restrict__ cb2,
                              const float* __restrict__ cW3, const float* __restrict__ cb3,
                              float* __restrict__ out)
{
    __shared__ __align__(16) float sh[2816];         // tail scratch
    __shared__ __align__(16) float cfv[5*128];
    __shared__ float zq5[5*128];
    __shared__ float wbest[5][4];
    __shared__ int   widx[5][4];
    __shared__ int   bidx[5];

    int g = blockIdx.x, t = threadIdx.x;             // 640 threads
    int k = t >> 7, c = t & 127;

    // ---- cf: divide ----
    cfv[k*128 + c] = g_cfnum[((size_t)g*5 + k)*128 + c] / (g_ssum[g*5 + k] + 1e-6f);
    __syncthreads();

    // ---- VQ: nearest codebook row per cluster (5 rows x 4 warps each) ----
    {
        int w4 = c >> 5, lane = c & 31;
        float4 fv = ((const float4*)(cfv + k*128))[lane];
        float best = 3.4e38f;
        int bi = 0;
        for (int rr = w4; rr < CBN; rr += 4) {
            const float4* cb4 = (const float4*)(codebook + (size_t)rr*128);
            float4 cv = cb4[lane];
            float dx = cv.x - fv.x, dy = cv.y - fv.y, dz = cv.z - fv.z, dw = cv.w - fv.w;
            float d = dx*dx + dy*dy + dz*dz + dw*dw;
            #pragma unroll
            for (int o = 16; o; o >>= 1) d += __shfl_xor_sync(0xffffffff, d, o);
            if (d < best) { best = d; bi = rr; }
        }
        if (lane == 0) { wbest[k][w4] = best; widx[k][w4] = bi; }
        __syncthreads();
        if (t < 5) {
            float bb = wbest[t][0]; int ii = widx[t][0];
            for (int j = 1; j < 4; j++)
                if (wbest[t][j] < bb || (wbest[t][j] == bb && widx[t][j] < ii)) { bb = wbest[t][j]; ii = widx[t][j]; }
            bidx[t] = ii;
        }
        __syncthreads();
        zq5[k*128 + c] = codebook[(size_t)bidx[k]*128 + c];
    }
    __syncthreads();

    // ---- tail: attention + gate + classifier ----
    float* r    = sh;            // 128
    float* qv   = sh + 128;      // 128
    float* kk   = sh + 256;      // 640
    float* vv   = sh + 896;      // 640
    float* sc   = sh + 1536;     // 20
    float* aw   = sh + 1568;     // 20
    float* attv = sh + 1600;     // 128
    float* attn = sh + 1728;     // 128
    float* g1   = sh + 1856;     // 64
    float* fus  = sh + 1920;     // 128
    float* z1   = sh + 2048;     // 512
    float* z2   = sh + 2560;     // 256

    if (t < 128) r[t] = g_res[g*128 + t]*(1.0f/NPGC);
    __syncthreads();

    if (t < 128) {
        float a = 0.0f;
        for (int k2 = 0; k2 < 128; k2++) a += r[k2]*Wq[k2*128 + t];
        qv[t] = a;
        float a5[5] = {0,0,0,0,0};
        for (int k2 = 0; k2 < 128; k2++) {
            float wv2 = Wk[k2*128 + t];
            #pragma unroll
            for (int j = 0; j < 5; j++) a5[j] += zq5[j*128 + k2]*wv2;
        }
        #pragma unroll
        for (int j = 0; j < 5; j++) kk[j*128 + t] = a5[j];
        float b5[5] = {0,0,0,0,0};
        for (int k2 = 0; k2 < 128; k2++) {
            float wv2 = Wv[k2*128 + t];
            #pragma unroll
            for (int j = 0; j < 5; j++) b5[j] += zq5[j*128 + k2]*wv2;
        }
        #pragma unroll
        for (int j = 0; j < 5; j++) vv[j*128 + t] = b5[j];
    }
    __syncthreads();

    if (t < 20) {
        int hh = t/5, j = t%5;
        float s = 0.0f;
        for (int d2 = 0; d2 < 32; d2++) s += qv[hh*32 + d2]*kk[j*128 + hh*32 + d2];
        sc[t] = s*0.17677669529663687f;              // 1/sqrt(32)
    }
    __syncthreads();
    if (t < 4) {
        float m = -1e30f;
        #pragma unroll
        for (int j = 0; j < 5; j++) m = fmaxf(m, sc[t*5 + j]);
        float e[5], s = 0.0f;
        #pragma unroll
        for (int j = 0; j < 5; j++) { e[j] = expf(sc[t*5 + j] - m); s += e[j]; }
        float inv = 1.0f/s;
        #pragma unroll
        for (int j = 0; j < 5; j++) aw[t*5 + j] = e[j]*inv;
    }
    __syncthreads();
    if (t < 128) {
        int hh = t >> 5;
        float a = 0.0f;
        #pragma unroll
        for (int j = 0; j < 5; j++) a += aw[hh*5 + j]*vv[j*128 + t];
        attv[t] = a;
    }
    __syncthreads();
    if (t < 128) {
        float a = 0.0f;
        for (int k2 = 0; k2 < 128; k2++) a += attv[k2]*Wo[k2*128 + t];
        attn[t] = a;
    }
    __syncthreads();
    if (t < 64) {
        float a = gb1[t];
        for (int k2 = 0; k2 < 128; k2++) a += r[k2]*gW1[k2*64 + t];
        for (int k2 = 0; k2 < 128; k2++) a += attn[k2]*gW1[(128 + k2)*64 + t];
        g1[t] = fmaxf(a, 0.0f);
    }
    __syncthreads();
    if (t < 128) {
        float a = gb2[t];
        for (int k2 = 0; k2 < 64; k2++) a += g1[k2]*gW2[k2*128 + t];
        float gg = 1.0f/(1.0f + expf(-a));
        fus[t] = gg*r[t] + (1.0f - gg)*attn[t];
    }
    __syncthreads();
    if (t < 512) {
        float a = cb1[t];
        for (int k2 = 0; k2 < 128; k2++) a += fus[k2]*cW1[k2*512 + t];
        z1[t] = fmaxf(a, 0.0f);
    }
    __syncthreads();
    if (t < 256) {
        float a = cb2[t];
        for (int k2 = 0; k2 < 512; k2++) a += z1[k2]*cW2[k2*256 + t];
        z2[t] = fmaxf(a, 0.0f);
    }
    __syncthreads();
    if (t < 2) {
        float a = cb3[t];
        for (int k2 = 0; k2 < 256; k2++) a += z2[k2]*cW3[k2*2 + t];
        out[g*2 + t] = a;
    }
}

// ---------------- host launch ----------------
extern "C" void kernel_launch(void* const* d_in, const int* in_sizes, int n_in,
                              void* d_out, int out_size) {
    (void)in_sizes; (void)n_in; (void)out_size;
    const int*   x     = (const int*)d_in[0];
    const int*   ei    = (const int*)d_in[1];
    const float* emb   = (const float*)d_in[3];
    const float* gW1   = (const float*)d_in[4];
    const float* gb1v  = (const float*)d_in[5];
    const float* gW2   = (const float*)d_in[6];
    const float* gb2v  = (const float*)d_in[7];
    const float* bng   = (const float*)d_in[8];
    const float* bnb   = (const float*)d_in[9];
    const float* pW1   = (const float*)d_in[10];
    const float* pb1   = (const float*)d_in[11];
    const float* pW2   = (const float*)d_in[12];
    const float* pb2   = (const float*)d_in[13];
    const float* Wq    = (const float*)d_in[14];
    const float* Wk    = (const float*)d_in[15];
    const float* Wv    = (const float*)d_in[16];
    const float* Wo    = (const float*)d_in[17];
    const float* gateW1= (const float*)d_in[18];
    const float* gateb1= (const float*)d_in[19];
    const float* gateW2= (const float*)d_in[20];
    const float* gateb2= (const float*)d_in[21];
    const float* cbk   = (const float*)d_in[22];
    const float* cW1   = (const float*)d_in[23];
    const float* cb1   = (const float*)d_in[24];
    const float* cW2   = (const float*)d_in[25];
    const float* cb2   = (const float*)d_in[26];
    const float* cW3   = (const float*)d_in[27];
    const float* cb3   = (const float*)d_in[28];
    float* out = (float*)d_out;

    bf16 *w1hi, *w1lo, *w2hi, *w2lo, *pwhi, *pwlo;
    float *ppb1;
    cudaGetSymbolAddress((void**)&w1hi, g_w1hi);
    cudaGetSymbolAddress((void**)&w1lo, g_w1lo);
    cudaGetSymbolAddress((void**)&w2hi, g_w2hi);
    cudaGetSymbolAddress((void**)&w2lo, g_w2lo);
    cudaGetSymbolAddress((void**)&pwhi, g_pwhi);
    cudaGetSymbolAddress((void**)&pwlo, g_pwlo);
    cudaGetSymbolAddress((void**)&ppb1, g_pb1);

    cudaFuncSetAttribute(ginlayer, cudaFuncAttributeMaxDynamicSharedMemorySize, GIN_SMEM);

    setup_kernel<<<64 + 1024, 512>>>(ei, x, emb, gW1, gW2, pW1, pb1);

    for (int l = 0; l < 3; l++) {
        ginlayer<<<NN/32, 256, GIN_SMEM>>>(
            w1hi + (size_t)l*DD*H2D, w1lo + (size_t)l*DD*H2D,
            w2hi + (size_t)l*H2D*DD, w2lo + (size_t)l*H2D*DD,
            gb1v + l*H2D, gb2v + l*DD, bng + l*DD, bnb + l*DD,
            pwhi, pwlo, ppb1, pW2, pb2,
            (l == 2) ? 1 : 0);
    }

    cfpartial_kernel<<<BB*8, 640>>>();
    finale_kernel<<<BB, 640>>>(cbk, Wq, Wk, Wv, Wo, gateW1, gateb1, gateW2, gateb2,
                               cW1, cb1, cW2, cb2, cW3, cb3, out);
}